// round 10
// baseline (speedup 1.0000x reference)
#include <cuda_runtime.h>
#include <cstdint>

// LSEP loss: log1p( sum_i [ exp(-x[i,y_i]) * sum_j exp(x[i,j]) ] - B )
//
// Two-phase single kernel:
//  Phase 1: thread-per-row gathers pos = x[row, tgt[row]], stores
//           g_e[row] = exp(-pos). (~0.5us, latency-bound)
//  Grid barrier: GRID=296 = exactly 2 CTAs/SM -> whole grid co-resident in
//           one wave (spin is deadlock-free). Counter reset by last block.
//  Phase 2: flat float4 grid-stride over all B*85 float4s. Every float4 is
//           inside one row (340/4==85), so row = i/85 (mul-shift) and
//           g_e[row] is an L1-resident broadcast. 8-way unroll keeps 8
//           LDG.128 per warp in flight continuously. Perfect lane balance,
//           ~0.55 warp-instrs per float4 -> memory-bound by construction.
// fp32 per-thread accumulator (~74 adds, ~1e-6 rel err), fp64 deterministic
// tree reduction after. Fused last-block-done final reduce.

#define NCLS    340
#define N4PR    85              // float4s per row
#define GRID    296             // 148 SMs * 2 CTAs: co-resident wave
#define BLOCK   256
#define WPB     (BLOCK / 32)
#define NTHREADS (GRID * BLOCK)
#define MAXB    65536

__device__ float        g_e[MAXB];
__device__ double       g_partials[GRID];
__device__ unsigned int g_bar   = 0;     // phase barrier; reset by last block
__device__ unsigned int g_count = 0;     // wraps via atomicInc -> replay-safe

__device__ __forceinline__ float exp4(float4 v) {
    return __expf(v.x) + __expf(v.y) + __expf(v.z) + __expf(v.w);
}

__global__ __launch_bounds__(BLOCK)
void lsep_flat_kernel(const float* __restrict__ x,
                      const int*   __restrict__ tgt,
                      float*       __restrict__ out,
                      int B)
{
    const int tid  = threadIdx.x;
    const int gtid = blockIdx.x * BLOCK + tid;

    // ---------------- phase 1: per-row exp(-pos) ----------------
    if (gtid < B) {
        int y = tgt[gtid];
        y = min(max(y, 0), NCLS - 1);
        float pos = __ldg(x + (size_t)gtid * NCLS + y);
        g_e[gtid] = __expf(-pos);
    }
    __threadfence();                       // make g_e[gtid] globally visible
    __syncthreads();

    // ---------------- grid barrier (one co-resident wave) ----------------
    if (tid == 0) {
        atomicAdd(&g_bar, 1u);
        unsigned int v;
        do {
            asm volatile("ld.acquire.gpu.u32 %0, [%1];"
                         : "=r"(v) : "l"(&g_bar));
        } while (v < GRID);
    }
    __syncthreads();

    // ---------------- phase 2: flat float4 reduction ----------------
    const float4* __restrict__ x4 = (const float4*)x;
    const int N4 = B * N4PR;

    float acc = 0.0f;
    int i = gtid;

    // full batches of 8 (front-batched LDG.128 -> continuous MLP=8)
    while (i + 7 * NTHREADS < N4) {
        float4 v0 = x4[i];
        float4 v1 = x4[i + 1 * NTHREADS];
        float4 v2 = x4[i + 2 * NTHREADS];
        float4 v3 = x4[i + 3 * NTHREADS];
        float4 v4 = x4[i + 4 * NTHREADS];
        float4 v5 = x4[i + 5 * NTHREADS];
        float4 v6 = x4[i + 6 * NTHREADS];
        float4 v7 = x4[i + 7 * NTHREADS];

        acc += __ldg(&g_e[(unsigned)(i              ) / N4PR]) * exp4(v0);
        acc += __ldg(&g_e[(unsigned)(i + 1 * NTHREADS) / N4PR]) * exp4(v1);
        acc += __ldg(&g_e[(unsigned)(i + 2 * NTHREADS) / N4PR]) * exp4(v2);
        acc += __ldg(&g_e[(unsigned)(i + 3 * NTHREADS) / N4PR]) * exp4(v3);
        acc += __ldg(&g_e[(unsigned)(i + 4 * NTHREADS) / N4PR]) * exp4(v4);
        acc += __ldg(&g_e[(unsigned)(i + 5 * NTHREADS) / N4PR]) * exp4(v5);
        acc += __ldg(&g_e[(unsigned)(i + 6 * NTHREADS) / N4PR]) * exp4(v6);
        acc += __ldg(&g_e[(unsigned)(i + 7 * NTHREADS) / N4PR]) * exp4(v7);

        i += 8 * NTHREADS;
    }
    // tail
    for (; i < N4; i += NTHREADS) {
        float4 v = x4[i];
        acc += __ldg(&g_e[(unsigned)i / N4PR]) * exp4(v);
    }

    double dacc = (double)acc;             // one convert per thread

    // ---------------- block reduction (deterministic) ----------------
    #pragma unroll
    for (int o = 16; o; o >>= 1)
        dacc += __shfl_xor_sync(0xffffffffu, dacc, o);

    __shared__ double sacc[WPB];
    __shared__ bool   is_last;
    if ((tid & 31) == 0) sacc[tid >> 5] = dacc;
    __syncthreads();

    if (tid == 0) {
        double t = 0.0;
        #pragma unroll
        for (int w = 0; w < WPB; w++) t += sacc[w];
        g_partials[blockIdx.x] = t;
        __threadfence();
        unsigned int old = atomicInc(&g_count, GRID - 1);   // wraps to 0
        is_last = (old == GRID - 1);
    }
    __syncthreads();

    // ---------------- last block: final reduce + log1p ----------------
    if (is_last) {
        __threadfence();
        __shared__ double sfin[BLOCK];
        double t = 0.0;
        for (int k = tid; k < GRID; k += BLOCK) t += g_partials[k];
        sfin[tid] = t;
        __syncthreads();
        #pragma unroll
        for (int o = BLOCK / 2; o; o >>= 1) {
            if (tid < o) sfin[tid] += sfin[tid + o];
            __syncthreads();
        }
        if (tid == 0) {
            out[0] = (float)log1p(sfin[0] - (double)B);
            g_bar = 0;                      // reset phase barrier for replay
        }
    }
}

extern "C" void kernel_launch(void* const* d_in, const int* in_sizes, int n_in,
                              void* d_out, int out_size)
{
    const float* x   = (const float*)d_in[0];
    const int*   tgt = (const int*)d_in[1];
    float*       out = (float*)d_out;

    int B = in_sizes[0] / NCLS;   // 65536
    if (B > MAXB) B = MAXB;

    lsep_flat_kernel<<<GRID, BLOCK>>>(x, tgt, out, B);
}

// round 11
// speedup vs baseline: 1.2145x; 1.2145x over previous
#include <cuda_runtime.h>

// LSEP loss: log1p( sum_i [ exp(-x[i,y_i]) * sum_j exp(x[i,j]) ] - B )
//
// Balanced 3-row groups: each warp iteration consumes 3 consecutive rows =
// 255 float4 = 8 chunks of 32 lanes (only lane31/k7 idle -> 1/256 waste vs
// 11/96 in row-per-warp). Chunk q = lane+32k is loop-invariant, so its row
// (q/85) and the e-select predicates hoist out of the loop. pos values are
// gathered one group ahead using targets loaded two groups ahead (R9's
// pipeline), so the y->pos chain never stalls. fp32 per-lane accumulator in
// the hot loop (fp64 DADD was the R8 bottleneck); fp64 deterministic tree
// reduction after. Fused last-block-done reduce (self-resetting counter ->
// graph-replay safe).

#define NCLS   340
#define RPG    3               // rows per group
#define C4G    255             // float4s per group (3*85)
#define GRID   592             // 148 SMs * 4 CTAs (regs ~60)
#define BLOCK  256
#define WPB    (BLOCK / 32)

__device__ double       g_partials[GRID];
__device__ unsigned int g_count = 0;     // wraps via atomicInc -> replay-safe

__device__ __forceinline__ float exp4(float4 v) {
    return __expf(v.x) + __expf(v.y) + __expf(v.z) + __expf(v.w);
}

__global__ __launch_bounds__(BLOCK)
void lsep_grp_kernel(const float* __restrict__ x,
                     const int*   __restrict__ tgt,
                     float*       __restrict__ out,
                     int B)
{
    const int lane   = threadIdx.x & 31;
    const int warp   = threadIdx.x >> 5;
    const int wglob  = blockIdx.x * WPB + warp;
    const int wtotal = GRID * WPB;

    const int nfull = B / RPG;                 // full 3-row groups
    const int rem   = B - nfull * RPG;         // leftover rows (1 for B=65536)

    float acc = 0.0f;

    int p = wglob;
    if (p < nfull) {
        // ---- prologue ----
        const int* tp = tgt + p * RPG;
        int a0 = tp[0], a1 = tp[1], a2 = tp[2];            // targets, group p
        const float* xb = x + (size_t)p * RPG * NCLS;
        float pc0 = __ldg(xb + a0);                        // pos, group p
        float pc1 = __ldg(xb + NCLS + a1);
        float pc2 = __ldg(xb + 2 * NCLS + a2);

        int p1 = p + wtotal;
        int b0 = 0, b1 = 0, b2 = 0;                        // targets, group p+1
        if (p1 < nfull) {
            const int* tn = tgt + p1 * RPG;
            b0 = tn[0]; b1 = tn[1]; b2 = tn[2];
        }

        for (;;) {
            const int pn  = p + wtotal;
            const int pnn = p + 2 * wtotal;
            const bool more = pn < nfull;

            // pos gathers for NEXT group (targets resident since last iter)
            float pn0 = 0.f, pn1 = 0.f, pn2 = 0.f;
            if (more) {
                const float* xn = x + (size_t)pn * RPG * NCLS;
                pn0 = __ldg(xn + b0);
                pn1 = __ldg(xn + NCLS + b1);
                pn2 = __ldg(xn + 2 * NCLS + b2);
            }
            // targets for group after next
            int c0 = 0, c1 = 0, c2 = 0;
            if (pnn < nfull) {
                const int* tn = tgt + pnn * RPG;
                c0 = tn[0]; c1 = tn[1]; c2 = tn[2];
            }

            // ---- current group: 8 front-batched chunk loads ----
            const float4* g4 = (const float4*)(x + (size_t)p * RPG * NCLS);
            float4 v0 = g4[lane];
            float4 v1 = g4[lane + 32];
            float4 v2 = g4[lane + 64];
            float4 v3 = g4[lane + 96];
            float4 v4 = g4[lane + 128];
            float4 v5 = g4[lane + 160];
            float4 v6 = g4[lane + 192];
            float4 v7;
            const bool k7ok = (lane + 224) < C4G;          // lane 31 skips
            if (k7ok) v7 = g4[lane + 224];

            const float e0 = __expf(-pc0);
            const float e1 = __expf(-pc1);
            const float e2 = __expf(-pc2);

            // per-chunk row select: q = lane + 32k (loop-invariant predicates)
            #define EK(k) ((lane + 32*(k)) < 85 ? e0 : \
                           (lane + 32*(k)) < 170 ? e1 : e2)
            acc += EK(0) * exp4(v0);
            acc += EK(1) * exp4(v1);
            acc += EK(2) * exp4(v2);
            acc += EK(3) * exp4(v3);
            acc += EK(4) * exp4(v4);
            acc += EK(5) * exp4(v5);
            acc += EK(6) * exp4(v6);
            if (k7ok) acc += EK(7) * exp4(v7);
            #undef EK

            if (!more) break;
            pc0 = pn0; pc1 = pn1; pc2 = pn2;
            b0 = c0; b1 = c1; b2 = c2;
            p = pn;
        }
    }

    // ---- remainder rows (B % 3): one warp, simple path ----
    if (wglob == 0) {
        for (int r = 0; r < rem; r++) {
            const int row = nfull * RPG + r;
            const float* xr = x + (size_t)row * NCLS;
            const float4* r4 = (const float4*)xr;
            float s = exp4(r4[lane]) + exp4(r4[lane + 32]);
            if (lane < 21) s += exp4(r4[lane + 64]);
            float pos = __ldg(xr + tgt[row]);
            acc += s * __expf(-pos);
        }
    }

    double dacc = (double)acc;                 // one convert per lane

    // ---- block reduction (deterministic) ----
    #pragma unroll
    for (int o = 16; o; o >>= 1)
        dacc += __shfl_xor_sync(0xffffffffu, dacc, o);

    __shared__ double sacc[WPB];
    __shared__ bool   is_last;
    if (lane == 0) sacc[warp] = dacc;
    __syncthreads();

    if (threadIdx.x == 0) {
        double t = 0.0;
        #pragma unroll
        for (int i = 0; i < WPB; i++) t += sacc[i];
        g_partials[blockIdx.x] = t;
        __threadfence();
        unsigned int old = atomicInc(&g_count, GRID - 1);  // wraps to 0
        is_last = (old == GRID - 1);
    }
    __syncthreads();

    // ---- last block: deterministic final reduce + log1p ----
    if (is_last) {
        __threadfence();
        __shared__ double sfin[BLOCK];
        double t = 0.0;
        for (int i = threadIdx.x; i < GRID; i += BLOCK)
            t += g_partials[i];
        sfin[threadIdx.x] = t;
        __syncthreads();
        #pragma unroll
        for (int o = BLOCK / 2; o; o >>= 1) {
            if (threadIdx.x < o) sfin[threadIdx.x] += sfin[threadIdx.x + o];
            __syncthreads();
        }
        if (threadIdx.x == 0)
            out[0] = (float)log1p(sfin[0] - (double)B);
    }
}

extern "C" void kernel_launch(void* const* d_in, const int* in_sizes, int n_in,
                              void* d_out, int out_size)
{
    const float* x   = (const float*)d_in[0];
    const int*   tgt = (const int*)d_in[1];
    float*       out = (float*)d_out;

    int B = in_sizes[0] / NCLS;   // 65536

    lsep_grp_kernel<<<GRID, BLOCK>>>(x, tgt, out, B);
}

// round 12
// speedup vs baseline: 1.3617x; 1.1212x over previous
#include <cuda_runtime.h>

// LSEP loss: log1p( sum_i [ exp(-x[i,y_i]) * sum_j exp(x[i,j]) ] - B )
//
// R11 balanced 3-row groups (255 float4 = 8 chunks of 32 lanes, 1/256 lane
// waste) with ONE change: __launch_bounds__(256, 4) raises the register
// budget to 64/thread. R11 compiled to 32 regs, which physically cannot hold
// 8 front-batched float4 loads -> ptxas split the batch and MLP never
// materialized. With 64 regs all 8 LDG.128 issue back-to-back (4KB in flight
// per warp, continuously). GRID=592 = 4 CTAs/SM kept (occupancy >50% has
// consistently regressed: cross-CTA L1tex queue contention). pos gathered one
// group ahead, targets two ahead; fp32 hot-loop accumulator; fp64
// deterministic tree reduction; fused last-block-done finish.

#define NCLS   340
#define RPG    3               // rows per group
#define C4G    255             // float4s per group (3*85)
#define GRID   592             // 148 SMs * 4 CTAs
#define BLOCK  256
#define WPB    (BLOCK / 32)

__device__ double       g_partials[GRID];
__device__ unsigned int g_count = 0;     // wraps via atomicInc -> replay-safe

__device__ __forceinline__ float exp4(float4 v) {
    return __expf(v.x) + __expf(v.y) + __expf(v.z) + __expf(v.w);
}

__global__ __launch_bounds__(BLOCK, 4)   // 64-reg budget, 4 CTAs/SM
void lsep_grp_kernel(const float* __restrict__ x,
                     const int*   __restrict__ tgt,
                     float*       __restrict__ out,
                     int B)
{
    const int lane   = threadIdx.x & 31;
    const int warp   = threadIdx.x >> 5;
    const int wglob  = blockIdx.x * WPB + warp;
    const int wtotal = GRID * WPB;

    const int nfull = B / RPG;                 // full 3-row groups
    const int rem   = B - nfull * RPG;         // leftover rows (1 for B=65536)

    float acc = 0.0f;

    int p = wglob;
    if (p < nfull) {
        // ---- prologue ----
        const int* tp = tgt + p * RPG;
        int a0 = tp[0], a1 = tp[1], a2 = tp[2];            // targets, group p
        const float* xb = x + (size_t)p * RPG * NCLS;
        float pc0 = __ldg(xb + a0);                        // pos, group p
        float pc1 = __ldg(xb + NCLS + a1);
        float pc2 = __ldg(xb + 2 * NCLS + a2);

        int p1 = p + wtotal;
        int b0 = 0, b1 = 0, b2 = 0;                        // targets, group p+1
        if (p1 < nfull) {
            const int* tn = tgt + p1 * RPG;
            b0 = tn[0]; b1 = tn[1]; b2 = tn[2];
        }

        for (;;) {
            const int pn  = p + wtotal;
            const int pnn = p + 2 * wtotal;
            const bool more = pn < nfull;

            // ---- current group: 8 front-batched chunk loads FIRST ----
            const float4* g4 = (const float4*)(x + (size_t)p * RPG * NCLS);
            float4 v0 = g4[lane];
            float4 v1 = g4[lane + 32];
            float4 v2 = g4[lane + 64];
            float4 v3 = g4[lane + 96];
            float4 v4 = g4[lane + 128];
            float4 v5 = g4[lane + 160];
            float4 v6 = g4[lane + 192];
            float4 v7;
            const bool k7ok = (lane + 224) < C4G;          // lane 31 skips
            if (k7ok) v7 = g4[lane + 224];

            // pos gathers for NEXT group (targets resident since last iter)
            float pn0 = 0.f, pn1 = 0.f, pn2 = 0.f;
            if (more) {
                const float* xn = x + (size_t)pn * RPG * NCLS;
                pn0 = __ldg(xn + b0);
                pn1 = __ldg(xn + NCLS + b1);
                pn2 = __ldg(xn + 2 * NCLS + b2);
            }
            // targets for group after next
            int c0 = 0, c1 = 0, c2 = 0;
            if (pnn < nfull) {
                const int* tn = tgt + pnn * RPG;
                c0 = tn[0]; c1 = tn[1]; c2 = tn[2];
            }

            const float e0 = __expf(-pc0);
            const float e1 = __expf(-pc1);
            const float e2 = __expf(-pc2);

            // per-chunk row select: q = lane + 32k (loop-invariant predicates)
            #define EK(k) ((lane + 32*(k)) < 85 ? e0 : \
                           (lane + 32*(k)) < 170 ? e1 : e2)
            acc += EK(0) * exp4(v0);
            acc += EK(1) * exp4(v1);
            acc += EK(2) * exp4(v2);
            acc += EK(3) * exp4(v3);
            acc += EK(4) * exp4(v4);
            acc += EK(5) * exp4(v5);
            acc += EK(6) * exp4(v6);
            if (k7ok) acc += EK(7) * exp4(v7);
            #undef EK

            if (!more) break;
            pc0 = pn0; pc1 = pn1; pc2 = pn2;
            b0 = c0; b1 = c1; b2 = c2;
            p = pn;
        }
    }

    // ---- remainder rows (B % 3): one warp, simple path ----
    if (wglob == 0) {
        for (int r = 0; r < rem; r++) {
            const int row = nfull * RPG + r;
            const float* xr = x + (size_t)row * NCLS;
            const float4* r4 = (const float4*)xr;
            float s = exp4(r4[lane]) + exp4(r4[lane + 32]);
            if (lane < 21) s += exp4(r4[lane + 64]);
            float pos = __ldg(xr + tgt[row]);
            acc += s * __expf(-pos);
        }
    }

    double dacc = (double)acc;                 // one convert per lane

    // ---- block reduction (deterministic) ----
    #pragma unroll
    for (int o = 16; o; o >>= 1)
        dacc += __shfl_xor_sync(0xffffffffu, dacc, o);

    __shared__ double sacc[WPB];
    __shared__ bool   is_last;
    if (lane == 0) sacc[warp] = dacc;
    __syncthreads();

    if (threadIdx.x == 0) {
        double t = 0.0;
        #pragma unroll
        for (int i = 0; i < WPB; i++) t += sacc[i];
        g_partials[blockIdx.x] = t;
        __threadfence();
        unsigned int old = atomicInc(&g_count, GRID - 1);  // wraps to 0
        is_last = (old == GRID - 1);
    }
    __syncthreads();

    // ---- last block: deterministic final reduce + log1p ----
    if (is_last) {
        __threadfence();
        __shared__ double sfin[BLOCK];
        double t = 0.0;
        for (int i = threadIdx.x; i < GRID; i += BLOCK)
            t += g_partials[i];
        sfin[threadIdx.x] = t;
        __syncthreads();
        #pragma unroll
        for (int o = BLOCK / 2; o; o >>= 1) {
            if (threadIdx.x < o) sfin[threadIdx.x] += sfin[threadIdx.x + o];
            __syncthreads();
        }
        if (threadIdx.x == 0)
            out[0] = (float)log1p(sfin[0] - (double)B);
    }
}

extern "C" void kernel_launch(void* const* d_in, const int* in_sizes, int n_in,
                              void* d_out, int out_size)
{
    const float* x   = (const float*)d_in[0];
    const int*   tgt = (const int*)d_in[1];
    float*       out = (float*)d_out;

    int B = in_sizes[0] / NCLS;   // 65536

    lsep_grp_kernel<<<GRID, BLOCK>>>(x, tgt, out, B);
}